// round 11
// baseline (speedup 1.0000x reference)
#include <cuda_runtime.h>
#include <cuda_bf16.h>
#include <cstdint>
#include <math.h>

#define BATCH 32
#define HW    1024
#define CCH   256
#define FF    64

// ---------------- scratch (allocation-free) ----------------
__device__ float g_emb[BATCH * HW * FF];
__device__ float g_short[BATCH * HW * CCH];
__device__ float g_T[BATCH * HW];
__device__ float g_sq[BATCH * HW];
__device__ float g_iz[BATCH * HW];
__device__ __nv_bfloat16 g_wEh[FF * CCH];          // emb_W hi
__device__ __nv_bfloat16 g_wEl[FF * CCH];
__device__ __nv_bfloat16 g_wAh[CCH * CCH];         // attn_W hi
__device__ __nv_bfloat16 g_wAl[CCH * CCH];
__device__ __nv_bfloat16 g_ebh[BATCH * HW * FF];   // emb hi
__device__ __nv_bfloat16 g_ebl[BATCH * HW * FF];   // emb lo
__device__ __nv_bfloat16 g_sth[BATCH * CCH * HW];  // shortcut^T hi [b][c][j]
__device__ __nv_bfloat16 g_stl[BATCH * CCH * HW];  // shortcut^T lo
__device__ __nv_bfloat16 g_ev[BATCH * HW * HW];    // exp(v)

// ---------------- helpers ----------------
__device__ __forceinline__ uint32_t smem_u32(const void* p) {
    uint32_t a;
    asm("{ .reg .u64 t; cvta.to.shared.u64 t, %1; cvt.u32.u64 %0, t; }" : "=r"(a) : "l"(p));
    return a;
}
__device__ __forceinline__ void ldsm4(uint32_t& r0, uint32_t& r1, uint32_t& r2, uint32_t& r3,
                                      uint32_t addr) {
    asm volatile("ldmatrix.sync.aligned.m8n8.x4.shared.b16 {%0,%1,%2,%3}, [%4];"
        : "=r"(r0), "=r"(r1), "=r"(r2), "=r"(r3) : "r"(addr));
}
__device__ __forceinline__ void mma16816(float* d, const uint32_t* a, uint32_t b0, uint32_t b1) {
    asm volatile("mma.sync.aligned.m16n8k16.row.col.f32.bf16.bf16.f32 "
        "{%0,%1,%2,%3}, {%4,%5,%6,%7}, {%8,%9}, {%0,%1,%2,%3};"
        : "+f"(d[0]), "+f"(d[1]), "+f"(d[2]), "+f"(d[3])
        : "r"(a[0]), "r"(a[1]), "r"(a[2]), "r"(a[3]), "r"(b0), "r"(b1));
}
__device__ __forceinline__ uint32_t pack2bf(float a, float b) {
    __nv_bfloat162 t = __floats2bfloat162_rn(a, b);
    return *(uint32_t*)&t;
}
__device__ __forceinline__ void cvt8(float4 a, float4 b, uint4& hu, uint4& lu) {
    __nv_bfloat16 h0 = __float2bfloat16(a.x), h1 = __float2bfloat16(a.y);
    __nv_bfloat16 h2 = __float2bfloat16(a.z), h3 = __float2bfloat16(a.w);
    __nv_bfloat16 h4 = __float2bfloat16(b.x), h5 = __float2bfloat16(b.y);
    __nv_bfloat16 h6 = __float2bfloat16(b.z), h7 = __float2bfloat16(b.w);
    __nv_bfloat162 p0; p0.x = h0; p0.y = h1;
    __nv_bfloat162 p1; p1.x = h2; p1.y = h3;
    __nv_bfloat162 p2; p2.x = h4; p2.y = h5;
    __nv_bfloat162 p3; p3.x = h6; p3.y = h7;
    hu.x = *(uint32_t*)&p0; hu.y = *(uint32_t*)&p1;
    hu.z = *(uint32_t*)&p2; hu.w = *(uint32_t*)&p3;
    lu.x = pack2bf(a.x - __bfloat162float(h0), a.y - __bfloat162float(h1));
    lu.y = pack2bf(a.z - __bfloat162float(h2), a.w - __bfloat162float(h3));
    lu.z = pack2bf(b.x - __bfloat162float(h4), b.y - __bfloat162float(h5));
    lu.w = pack2bf(b.z - __bfloat162float(h6), b.w - __bfloat162float(h7));
}
#define CPA(dst, src) asm volatile("cp.async.cg.shared.global [%0], [%1], 16;" :: "r"(dst), "l"(src))
#define CPC() asm volatile("cp.async.commit_group;" ::: "memory")
#define CPW(n) asm volatile("cp.async.wait_group %0;" :: "n"(n) : "memory")

// stage a [rows x 64 bf16] tile into XOR-swizzled smem (plain loads, gram only)
__device__ __forceinline__ void stage_tile(char* dst, const __nv_bfloat16* src,
                                           int srcStride, int tid) {
    #pragma unroll
    for (int m = 0; m < 4; m++) {
        int idx = tid + m * 256;
        int row = idx >> 3, c4 = idx & 7;
        *(uint4*)(dst + row * 128 + ((c4 ^ (row & 7)) << 4)) =
            *(const uint4*)(src + (size_t)row * srcStride + c4 * 8);
    }
}

// ---------------------------------------------------------------------------
// split fp32 -> bf16 hi/lo (weights only)
// ---------------------------------------------------------------------------
__global__ __launch_bounds__(256) void split_f32(
    const float* __restrict__ src, __nv_bfloat16* __restrict__ hi,
    __nv_bfloat16* __restrict__ lo, int n4)
{
    int i = blockIdx.x * 256 + threadIdx.x;
    if (i >= n4) return;
    float4 v = ((const float4*)src)[i];
    __nv_bfloat16 h0 = __float2bfloat16(v.x);
    __nv_bfloat16 h1 = __float2bfloat16(v.y);
    __nv_bfloat16 h2 = __float2bfloat16(v.z);
    __nv_bfloat16 h3 = __float2bfloat16(v.w);
    __nv_bfloat162 hp0; hp0.x = h0; hp0.y = h1;
    __nv_bfloat162 hp1; hp1.x = h2; hp1.y = h3;
    uint2 hu = {*(uint32_t*)&hp0, *(uint32_t*)&hp1};
    uint2 lu = {pack2bf(v.x - __bfloat162float(h0), v.y - __bfloat162float(h1)),
                pack2bf(v.z - __bfloat162float(h2), v.w - __bfloat162float(h3))};
    ((uint2*)hi)[i] = hu;
    ((uint2*)lo)[i] = lu;
}

// ---------------------------------------------------------------------------
// hmma_emb: emb = X @ emb_W^T + b. block 128 rows x 64 cols, 128 thr.
// A staged from fp32 x inline (LDG+cvt+STS); W via cp.async from splits.
// stage layout: AH 0, AL 16384, BH 32768, BL 40960; stage size 49152.
// ---------------------------------------------------------------------------
#define E_ST 49152
__device__ __forceinline__ void emb_w_stage(uint32_t sb, int sofs, int kk, int tid) {
    #pragma unroll
    for (int m = 0; m < 4; m++) {
        int idx = tid + m * 128;
        int row = idx >> 3, c4 = idx & 7;
        uint32_t sw = row * 128 + ((c4 ^ (row & 7)) << 4);
        CPA(sb + sofs + 32768 + sw, g_wEh + (size_t)row * 256 + kk + c4 * 8);
        CPA(sb + sofs + 40960 + sw, g_wEl + (size_t)row * 256 + kk + c4 * 8);
    }
}

__global__ void __launch_bounds__(128) hmma_emb(
    const float* __restrict__ x, const float* __restrict__ bias)
{
    extern __shared__ char smem[];
    uint32_t sb = smem_u32(smem);
    int tid = threadIdx.x, lane = tid & 31, warp = tid >> 5;
    int g = lane >> 3, l7 = lane & 7, r = lane >> 2, q = lane & 3;
    int i0 = blockIdx.x * 128;
    int wm = warp;
    int swr = tid & 7;

    float acc[2][8][4];
    #pragma unroll
    for (int mt = 0; mt < 2; mt++)
        #pragma unroll
        for (int n = 0; n < 8; n++)
            #pragma unroll
            for (int c = 0; c < 4; c++) acc[mt][n][c] = 0.f;

    float4 xr[16];
    // prologue
    emb_w_stage(sb, 0, 0, tid); CPC();
    {
        const float4* xs = (const float4*)&x[(size_t)(i0 + tid) * 256];
        #pragma unroll
        for (int v = 0; v < 16; v++) xr[v] = xs[v];
        #pragma unroll
        for (int c4 = 0; c4 < 8; c4++) {
            uint4 hu, lu;
            cvt8(xr[c4 * 2], xr[c4 * 2 + 1], hu, lu);
            uint32_t sw = tid * 128 + ((c4 ^ swr) << 4);
            *(uint4*)(smem + 0 + sw) = hu;
            *(uint4*)(smem + 16384 + sw) = lu;
        }
    }
    for (int kc = 0; kc < 4; kc++) {
        CPW(0);
        __syncthreads();
        int base = (kc & 1) * E_ST;
        int nbase = ((kc + 1) & 1) * E_ST;
        if (kc < 3) {
            emb_w_stage(sb, nbase, (kc + 1) * 64, tid); CPC();
            const float4* xs = (const float4*)&x[(size_t)(i0 + tid) * 256 + (kc + 1) * 64];
            #pragma unroll
            for (int v = 0; v < 16; v++) xr[v] = xs[v];
        }
        #pragma unroll
        for (int k = 0; k < 4; k++) {
            uint32_t ah[2][4], al[2][4];
            #pragma unroll
            for (int mt = 0; mt < 2; mt++) {
                int row = wm * 32 + mt * 16 + (g & 1) * 8 + l7;
                int c4 = k * 2 + (g >> 1);
                uint32_t off = base + row * 128 + ((c4 ^ (row & 7)) << 4);
                ldsm4(ah[mt][0], ah[mt][1], ah[mt][2], ah[mt][3], sb + 0 + off);
                ldsm4(al[mt][0], al[mt][1], al[mt][2], al[mt][3], sb + 16384 + off);
            }
            uint32_t bh[4][4], bl[4][4];
            #pragma unroll
            for (int nt = 0; nt < 4; nt++) {
                int row = nt * 16 + (g >> 1) * 8 + l7;
                int c4 = k * 2 + (g & 1);
                uint32_t off = base + row * 128 + ((c4 ^ (row & 7)) << 4);
                ldsm4(bh[nt][0], bh[nt][1], bh[nt][2], bh[nt][3], sb + 32768 + off);
                ldsm4(bl[nt][0], bl[nt][1], bl[nt][2], bl[nt][3], sb + 40960 + off);
            }
            #pragma unroll
            for (int mt = 0; mt < 2; mt++)
                #pragma unroll
                for (int nt = 0; nt < 4; nt++)
                    #pragma unroll
                    for (int h = 0; h < 2; h++) {
                        float* d = acc[mt][nt * 2 + h];
                        mma16816(d, ah[mt], bh[nt][h * 2], bh[nt][h * 2 + 1]);
                        mma16816(d, ah[mt], bl[nt][h * 2], bl[nt][h * 2 + 1]);
                        mma16816(d, al[mt], bh[nt][h * 2], bh[nt][h * 2 + 1]);
                    }
        }
        if (kc < 3) {
            #pragma unroll
            for (int c4 = 0; c4 < 8; c4++) {
                uint4 hu, lu;
                cvt8(xr[c4 * 2], xr[c4 * 2 + 1], hu, lu);
                uint32_t sw = nbase + tid * 128 + ((c4 ^ swr) << 4);
                *(uint4*)(smem + 0 + sw) = hu;
                *(uint4*)(smem + 16384 + sw) = lu;
            }
        }
    }
    // epilogue
    #pragma unroll
    for (int mt = 0; mt < 2; mt++)
        #pragma unroll
        for (int hh = 0; hh < 2; hh++) {
            int row = i0 + wm * 32 + mt * 16 + r + hh * 8;
            #pragma unroll
            for (int nt8 = 0; nt8 < 8; nt8++) {
                int col = nt8 * 8 + q * 2;
                float v0 = acc[mt][nt8][hh * 2 + 0] + bias[col];
                float v1 = acc[mt][nt8][hh * 2 + 1] + bias[col + 1];
                *(float2*)&g_emb[(size_t)row * 64 + col] = make_float2(v0, v1);
                __nv_bfloat16 h0 = __float2bfloat16(v0), h1 = __float2bfloat16(v1);
                __nv_bfloat162 hp; hp.x = h0; hp.y = h1;
                ((uint32_t*)g_ebh)[row * 32 + col / 2] = *(uint32_t*)&hp;
                ((uint32_t*)g_ebl)[row * 32 + col / 2] =
                    pack2bf(v0 - __bfloat162float(h0), v1 - __bfloat162float(h1));
            }
        }
}

// ---------------------------------------------------------------------------
// hmma_short: shortcut = X @ attn_W^T + b. block 128 x 128, 256 thr.
// A from fp32 x inline; W via cp.async. Transposed bf16 hi/lo epilogue.
// stage: AH 0, AL 16384, BH 32768, BL 49152; stage size 65536.
// ---------------------------------------------------------------------------
#define S_ST 65536
__device__ __forceinline__ void short_w_stage(uint32_t sb, int sofs, int c0, int kk, int tid) {
    #pragma unroll
    for (int m = 0; m < 4; m++) {
        int idx = tid + m * 256;
        int row = idx >> 3, c4 = idx & 7;
        uint32_t sw = row * 128 + ((c4 ^ (row & 7)) << 4);
        CPA(sb + sofs + 32768 + sw, g_wAh + (size_t)(c0 + row) * 256 + kk + c4 * 8);
        CPA(sb + sofs + 49152 + sw, g_wAl + (size_t)(c0 + row) * 256 + kk + c4 * 8);
    }
}

__global__ void __launch_bounds__(256) hmma_short(
    const float* __restrict__ x, const float* __restrict__ bias)
{
    extern __shared__ char smem[];
    uint32_t sb = smem_u32(smem);
    int tid = threadIdx.x, lane = tid & 31, warp = tid >> 5;
    int wm = warp >> 1, wn = warp & 1;
    int g = lane >> 3, l7 = lane & 7, r = lane >> 2, q = lane & 3;
    int i0 = blockIdx.x * 128, c0 = blockIdx.y * 128;
    int b = i0 >> 10;
    int arow = tid >> 1, ahalf = tid & 1;
    int aswr = arow & 7;

    float acc[2][8][4];
    #pragma unroll
    for (int mt = 0; mt < 2; mt++)
        #pragma unroll
        for (int n = 0; n < 8; n++)
            #pragma unroll
            for (int c = 0; c < 4; c++) acc[mt][n][c] = 0.f;

    float4 xr[8];
    short_w_stage(sb, 0, c0, 0, tid); CPC();
    {
        const float4* xs = (const float4*)&x[(size_t)(i0 + arow) * 256 + ahalf * 32];
        #pragma unroll
        for (int v = 0; v < 8; v++) xr[v] = xs[v];
        #pragma unroll
        for (int cc = 0; cc < 4; cc++) {
            uint4 hu, lu;
            cvt8(xr[cc * 2], xr[cc * 2 + 1], hu, lu);
            int c4 = ahalf * 4 + cc;
            uint32_t sw = arow * 128 + ((c4 ^ aswr) << 4);
            *(uint4*)(smem + 0 + sw) = hu;
            *(uint4*)(smem + 16384 + sw) = lu;
        }
    }
    for (int kc = 0; kc < 4; kc++) {
        CPW(0);
        __syncthreads();
        int base = (kc & 1) * S_ST;
        int nbase = ((kc + 1) & 1) * S_ST;
        if (kc < 3) {
            short_w_stage(sb, nbase, c0, (kc + 1) * 64, tid); CPC();
            const float4* xs = (const float4*)&x[(size_t)(i0 + arow) * 256 + (kc + 1) * 64 + ahalf * 32];
            #pragma unroll
            for (int v = 0; v < 8; v++) xr[v] = xs[v];
        }
        #pragma unroll
        for (int k = 0; k < 4; k++) {
            uint32_t ah[2][4], al[2][4];
            #pragma unroll
            for (int mt = 0; mt < 2; mt++) {
                int row = wm * 32 + mt * 16 + (g & 1) * 8 + l7;
                int c4 = k * 2 + (g >> 1);
                uint32_t off = base + row * 128 + ((c4 ^ (row & 7)) << 4);
                ldsm4(ah[mt][0], ah[mt][1], ah[mt][2], ah[mt][3], sb + 0 + off);
                ldsm4(al[mt][0], al[mt][1], al[mt][2], al[mt][3], sb + 16384 + off);
            }
            uint32_t bh[4][4], bl[4][4];
            #pragma unroll
            for (int nt = 0; nt < 4; nt++) {
                int row = wn * 64 + nt * 16 + (g >> 1) * 8 + l7;
                int c4 = k * 2 + (g & 1);
                uint32_t off = base + row * 128 + ((c4 ^ (row & 7)) << 4);
                ldsm4(bh[nt][0], bh[nt][1], bh[nt][2], bh[nt][3], sb + 32768 + off);
                ldsm4(bl[nt][0], bl[nt][1], bl[nt][2], bl[nt][3], sb + 49152 + off);
            }
            #pragma unroll
            for (int mt = 0; mt < 2; mt++)
                #pragma unroll
                for (int nt = 0; nt < 4; nt++)
                    #pragma unroll
                    for (int h = 0; h < 2; h++) {
                        float* d = acc[mt][nt * 2 + h];
                        mma16816(d, ah[mt], bh[nt][h * 2], bh[nt][h * 2 + 1]);
                        mma16816(d, ah[mt], bl[nt][h * 2], bl[nt][h * 2 + 1]);
                        mma16816(d, al[mt], bh[nt][h * 2], bh[nt][h * 2 + 1]);
                    }
        }
        if (kc < 3) {
            #pragma unroll
            for (int cc = 0; cc < 4; cc++) {
                uint4 hu, lu;
                cvt8(xr[cc * 2], xr[cc * 2 + 1], hu, lu);
                int c4 = ahalf * 4 + cc;
                uint32_t sw = nbase + arow * 128 + ((c4 ^ aswr) << 4);
                *(uint4*)(smem + 0 + sw) = hu;
                *(uint4*)(smem + 16384 + sw) = lu;
            }
        }
    }
    __syncthreads();

    // epilogue: +bias; fp32 to g_short; transpose via smem; bf16 hi/lo to g_sth/g_stl
    float* tb = (float*)smem;  // [128 cols][130]
    #pragma unroll
    for (int mt = 0; mt < 2; mt++)
        #pragma unroll
        for (int hh = 0; hh < 2; hh++) {
            int rl = wm * 32 + mt * 16 + r + hh * 8;
            #pragma unroll
            for (int nt8 = 0; nt8 < 8; nt8++) {
                int col = wn * 64 + nt8 * 8 + q * 2;
                float v0 = acc[mt][nt8][hh * 2 + 0] + bias[c0 + col];
                float v1 = acc[mt][nt8][hh * 2 + 1] + bias[c0 + col + 1];
                *(float2*)&g_short[(size_t)(i0 + rl) * 256 + c0 + col] = make_float2(v0, v1);
                tb[col * 130 + rl] = v0;
                tb[(col + 1) * 130 + rl] = v1;
            }
        }
    __syncthreads();
    {
        int c = tid >> 1, half = tid & 1;
        size_t tbase = ((size_t)b * CCH + c0 + c) * HW + (i0 & 1023) + half * 64;
        #pragma unroll
        for (int gch = 0; gch < 4; gch++) {
            uint32_t hp[8], lp[8];
            #pragma unroll
            for (int p = 0; p < 8; p++) {
                float v0 = tb[c * 130 + half * 64 + gch * 16 + p * 2];
                float v1 = tb[c * 130 + half * 64 + gch * 16 + p * 2 + 1];
                __nv_bfloat16 h0 = __float2bfloat16(v0), h1 = __float2bfloat16(v1);
                __nv_bfloat162 t; t.x = h0; t.y = h1;
                hp[p] = *(uint32_t*)&t;
                lp[p] = pack2bf(v0 - __bfloat162float(h0), v1 - __bfloat162float(h1));
            }
            *(uint4*)&g_sth[tbase + gch * 16]     = *(uint4*)&hp[0];
            *(uint4*)&g_sth[tbase + gch * 16 + 8] = *(uint4*)&hp[4];
            *(uint4*)&g_stl[tbase + gch * 16]     = *(uint4*)&lp[0];
            *(uint4*)&g_stl[tbase + gch * 16 + 8] = *(uint4*)&lp[4];
        }
    }
}

// ---------------------------------------------------------------------------
// aux: T = shortcut.thr_W + b; sq = |emb|^2. One warp per row.
// ---------------------------------------------------------------------------
__global__ __launch_bounds__(256) void aux_kernel(
    const float* __restrict__ thrW, const float* __restrict__ thrb)
{
    int w = threadIdx.x >> 5, lane = threadIdx.x & 31;
    int row = blockIdx.x * 8 + w;
    const float4* s4 = (const float4*)(g_short + (size_t)row * 256);
    const float4* t4 = (const float4*)thrW;
    float d = 0.f;
    #pragma unroll
    for (int m = 0; m < 2; m++) {
        float4 a = s4[lane + 32 * m], b = t4[lane + 32 * m];
        d += a.x * b.x + a.y * b.y + a.z * b.z + a.w * b.w;
    }
    float2 e = *(const float2*)&g_emb[(size_t)row * 64 + lane * 2];
    float s = e.x * e.x + e.y * e.y;
    #pragma unroll
    for (int off = 16; off; off >>= 1) {
        d += __shfl_xor_sync(0xffffffffu, d, off);
        s += __shfl_xor_sync(0xffffffffu, s, off);
    }
    if (lane == 0) { g_T[row] = d + thrb[0]; g_sq[row] = s; }
}

// ---------------------------------------------------------------------------
// gram_ev: HMMA 3-split gram -> ev = exp(exp(-d2)+mask-1), iz = 1/Z1
// ---------------------------------------------------------------------------
#define G_AH 0
#define G_AL 16384
#define G_BH 32768
#define G_BL 49152
#define G_SQJ 65536
#define G_ZC  66048
#define G_SMEM (G_ZC + 1024)

__global__ void __launch_bounds__(256) gram_ev()
{
    extern __shared__ char smem[];
    uint32_t sb = smem_u32(smem);
    float* sqj = (float*)(smem + G_SQJ);
    float* zc  = (float*)(smem + G_ZC);
    int tid = threadIdx.x, lane = tid & 31, warp = tid >> 5;
    int wm = warp >> 1, wn = warp & 1;
    int g = lane >> 3, l7 = lane & 7, r = lane >> 2, q = lane & 3;
    int b = blockIdx.y, i0 = blockIdx.x * 128;

    stage_tile(smem + G_AH, g_ebh + ((size_t)b * HW + i0) * FF, FF, tid);
    stage_tile(smem + G_AL, g_ebl + ((size_t)b * HW + i0) * FF, FF, tid);

    float sqi[2][2];
    int yi[2][2], xi[2][2];
    #pragma unroll
    for (int mt = 0; mt < 2; mt++)
        #pragma unroll
        for (int hh = 0; hh < 2; hh++) {
            int il = wm * 32 + mt * 16 + r + hh * 8;
            sqi[mt][hh] = g_sq[b * HW + i0 + il];
            int gi = i0 + il;
            yi[mt][hh] = gi >> 5; xi[mt][hh] = gi & 31;
        }
    float z1a[2][2] = {{0.f, 0.f}, {0.f, 0.f}};

    for (int jc = 0; jc < 8; jc++) {
        int j0 = jc * 128;
        stage_tile(smem + G_BH, g_ebh + ((size_t)b * HW + j0) * FF, FF, tid);
        stage_tile(smem + G_BL, g_ebl + ((size_t)b * HW + j0) * FF, FF, tid);
        if (tid < 128) sqj[tid] = g_sq[b * HW + j0 + tid];
        __syncthreads();

        float acc[2][8][4];
        #pragma unroll
        for (int mt = 0; mt < 2; mt++)
            #pragma unroll
            for (int n = 0; n < 8; n++)
                #pragma unroll
                for (int c = 0; c < 4; c++) acc[mt][n][c] = 0.f;

        #pragma unroll
        for (int k = 0; k < 4; k++) {
            uint32_t ah[2][4], al[2][4];
            #pragma unroll
            for (int mt = 0; mt < 2; mt++) {
                int row = wm * 32 + mt * 16 + (g & 1) * 8 + l7;
                int c4 = k * 2 + (g >> 1);
                uint32_t off = row * 128 + ((c4 ^ (row & 7)) << 4);
                ldsm4(ah[mt][0], ah[mt][1], ah[mt][2], ah[mt][3], sb + G_AH + off);
                ldsm4(al[mt][0], al[mt][1], al[mt][2], al[mt][3], sb + G_AL + off);
            }
            uint32_t bh[4][4], bl[4][4];
            #pragma unroll
            for (int nt = 0; nt < 4; nt++) {
                int row = wn * 64 + nt * 16 + (g >> 1) * 8 + l7;
                int c4 = k * 2 + (g & 1);
                uint32_t off = row * 128 + ((c4 ^ (row & 7)) << 4);
                ldsm4(bh[nt][0], bh[nt][1], bh[nt][2], bh[nt][3], sb + G_BH + off);
                ldsm4(bl[nt][0], bl[nt][1], bl[nt][2], bl[nt][3], sb + G_BL + off);
            }
            #pragma unroll
            for (int mt = 0; mt < 2; mt++)
                #pragma unroll
                for (int nt = 0; nt < 4; nt++)
                    #pragma unroll
                    for (int h = 0; h < 2; h++) {
                        float* d = acc[mt][nt * 2 + h];
                        mma16816(d, ah[mt], bh[nt][h * 2], bh[nt][h * 2 + 1]);
                        mma16816(d, ah[mt], bl[nt][h * 2], bl[nt][h * 2 + 1]);
                        mma16816(d, al[mt], bh[nt][h * 2], bh[nt][h * 2 + 1]);
                    }
        }
        #pragma unroll
        for (int mt = 0; mt < 2; mt++)
            #pragma unroll
            for (int nt8 = 0; nt8 < 8; nt8++) {
                int cloc = wn * 64 + nt8 * 8 + q * 2;
                int cj = j0 + cloc;
                float sj0 = sqj[cloc], sj1 = sqj[cloc + 1];
                int yj0 = cj >> 5, xj0 = cj & 31;
                int yj1 = (cj + 1) >> 5, xj1 = (cj + 1) & 31;
                #pragma unroll
                for (int hh = 0; hh < 2; hh++) {
                    int rowg = i0 + wm * 32 + mt * 16 + r + hh * 8;
                    float S0 = acc[mt][nt8][hh * 2 + 0];
                    float S1 = acc[mt][nt8][hh * 2 + 1];
                    float d20 = fmaxf(sqi[mt][hh] + sj0 - 2.f * S0, 0.f);
                    float d21 = fmaxf(sqi[mt][hh] + sj1 - 2.f * S1, 0.f);
                    int df0 = abs(yi[mt][hh] - yj0) + abs(xi[mt][hh] - xj0);
                    int df1 = abs(yi[mt][hh] - yj1) + abs(xi[mt][hh] - xj1);
                    float m0 = (df0 <= 32) ? df0 * (1.f / 32.f) : 0.f;
                    float m1 = (df1 <= 32) ? df1 * (1.f / 32.f) : 0.f;
                    float e0 = __expf(__expf(-d20) + m0 - 1.f);
                    float e1 = __expf(__expf(-d21) + m1 - 1.f);
                    z1a[mt][hh] += e0 + e1;
                    *(uint32_t*)&g_ev[((size_t)b * HW + rowg) * HW + cj] = pack2bf(e0, e1);
                }
            }
        __syncthreads();
    }
    #pragma unroll
    for (int mt = 0; mt < 2; mt++)
        #pragma unroll
        for (int hh = 0; hh < 2; hh++) {
            z1a[mt][hh] += __shfl_xor_sync(0xffffffffu, z1a[mt][hh], 1);
            z1a[mt][hh] += __shfl_xor_sync(0xffffffffu, z1a[mt][hh], 2);
        }
    if (q == 0) {
        #pragma unroll
        for (int mt = 0; mt < 2; mt++)
            #pragma unroll
            for (int hh = 0; hh < 2; hh++)
                zc[wn * 128 + wm * 32 + mt * 16 + r + hh * 8] = z1a[mt][hh];
    }
    __syncthreads();
    if (tid < 128)
        g_iz[b * HW + i0 + tid] = 1.f / (zc[tid] + zc[128 + tid]);
}

// ---------------------------------------------------------------------------
// attn_out (fused wgen): out = x + (w @ shortcut) / Z2.
// A tile computed in-kernel: w = exp(relu(ev*iz - T)), split hi/lo -> smem.
// B (shortcut^T splits) via cp.async double buffer.
// stage: AH 0, AL 16384, BH 32768, BL 49152; stage 65536. Ts @131072, zrow @135168.
// ---------------------------------------------------------------------------
#define O_ST 65536
#define O_TS 131072
#define O_ZR 135168
#define O_SMEM (O_ZR + 512)

__device__ __forceinline__ void o_b_stage(uint32_t sb, int sofs, int b, int c0,
                                          int j0, int tid) {
    #pragma unroll
    for (int m = 0; m < 4; m++) {
        int idx = tid + m * 256;
        int row = idx >> 3, c4 = idx & 7;
        uint32_t sw = row * 128 + ((c4 ^ (row & 7)) << 4);
        CPA(sb + sofs + 32768 + sw, g_sth + ((size_t)b * CCH + c0 + row) * HW + j0 + c4 * 8);
        CPA(sb + sofs + 49152 + sw, g_stl + ((size_t)b * CCH + c0 + row) * HW + j0 + c4 * 8);
    }
}

__global__ void __launch_bounds__(256) attn_out(
    const float* __restrict__ x, float* __restrict__ out)
{
    extern __shared__ char smem[];
    uint32_t sb = smem_u32(smem);
    float* Ts = (float*)(smem + O_TS);
    float* zrow = (float*)(smem + O_ZR);
    int tid = threadIdx.x, lane = tid & 31, warp = tid >> 5;
    int wm = warp >> 1, wn = warp & 1;
    int g = lane >> 3, l7 = lane & 7, r = lane >> 2, q = lane & 3;
    int b = blockIdx.z, i0 = blockIdx.x * 128, c0 = blockIdx.y * 128;
    int arow = tid >> 1, ahalf = tid & 1;
    int aswr = arow & 7;

    float acc[2][8][4];
    #pragma unroll
    for (int mt = 0; mt < 2; mt++)
        #pragma unroll
        for (int n = 0; n < 8; n++)
            #pragma unroll
            for (int c = 0; c < 4; c++) acc[mt][n][c] = 0.f;

    // prologue: Ts, iz, B chunk0, w chunk0
    #pragma unroll
    for (int m = 0; m < 4; m++) Ts[tid + m * 256] = g_T[b * HW + tid + m * 256];
    float iz = g_iz[b * HW + i0 + arow];
    size_t evb = ((size_t)b * HW + i0 + arow) * HW + ahalf * 32;
    float z2 = 0.f;
    o_b_stage(sb, 0, b, c0, 0, tid); CPC();
    __syncthreads();  // Ts visible

    uint4 evr[4];
    {
        const uint4* ep = (const uint4*)&g_ev[evb];
        #pragma unroll
        for (int cc = 0; cc < 4; cc++) evr[cc] = ep[cc];
        #pragma unroll
        for (int cc = 0; cc < 4; cc++) {
            uint32_t e4[4] = {evr[cc].x, evr[cc].y, evr[cc].z, evr[cc].w};
            uint32_t hq[4], lq[4];
            #pragma unroll
            for (int p = 0; p < 4; p++) {
                __nv_bfloat162 e2 = *(__nv_bfloat162*)&e4[p];
                int jj = ahalf * 32 + cc * 8 + p * 2;
                float w0 = __expf(fmaxf(fmaf(__bfloat162float(e2.x), iz, -Ts[jj]), 0.f));
                float w1 = __expf(fmaxf(fmaf(__bfloat162float(e2.y), iz, -Ts[jj + 1]), 0.f));
                z2 += w0 + w1;
                __nv_bfloat16 h0 = __float2bfloat16(w0), h1 = __float2bfloat16(w1);
                __nv_bfloat162 hp; hp.x = h0; hp.y = h1;
                hq[p] = *(uint32_t*)&hp;
                lq[p] = pack2bf(w0 - __bfloat162float(h0), w1 - __bfloat162float(h1));
            }
            int c4 = ahalf * 4 + cc;
            uint32_t sw = arow * 128 + ((c4 ^ aswr) << 4);
            *(uint4*)(smem + 0 + sw) = *(uint4*)hq;
            *(uint4*)(smem + 16384 + sw) = *(uint4*)lq;
        }
    }

    for (int kc = 0; kc < 16; kc++) {
        CPW(0);
        __syncthreads();
        int base = (kc & 1) * O_ST;
        int nbase = ((kc + 1) & 1) * O_ST;
        if (kc < 15) {
            o_b_stage(sb, nbase, b, c0, (kc + 1) * 64, tid); CPC();
            const uint4* ep = (const uint4*)&g_ev[evb + (kc + 1) * 64];
            #pragma unroll
            for (int cc = 0; cc < 4; cc++) evr[cc] = ep[cc];
        }
        #pragma unroll
        for (int k = 0; k < 4; k++) {
            uint32_t ah[2][4], al[2][4];
            #pragma unroll
            for (int mt = 0; mt < 2; mt++) {
                int row = wm * 32 + mt * 16 + (g & 1) * 8 + l7;
                int c4 = k * 2 + (g >> 1);
                uint32_t off = base + row * 128 + ((c4 ^ (row & 7)) << 4);
                ldsm4(ah[mt][0], ah[mt][1], ah[mt][2], ah[mt][3], sb + 0 + off);
                ldsm4(al[mt][0], al[mt][1], al[mt][2], al[mt][3], sb + 16384 + off);
            }
            uint32_t bh[4][4], bl[4][4];
            #pragma unroll
            for (int nt = 0; nt < 4; nt++) {
                int row = wn * 64 + nt * 16 + (g >> 1) * 8 + l7;
                int c4 = k * 2 + (g & 1);
                uint32_t off = base + row * 128 + ((c4 ^ (row & 7)) << 4);
                ldsm4(bh[nt][0], bh[nt][1], bh[nt][2], bh[nt][3], sb + 32768 + off);
                ldsm4(bl[nt][0], bl[nt][1], bl[nt][2], bl[nt][3], sb + 49152 + off);
            }
            #pragma unroll
            for (int mt = 0; mt < 2; mt++)
                #pragma unroll
                for (int nt = 0; nt < 4; nt++)
                    #pragma unroll
                    for (int h = 0; h < 2; h++) {
                        float* d = acc[mt][nt * 2 + h];
                        mma16816(d, ah[mt], bh[nt][h * 2], bh[nt][h * 2 + 1]);
                        mma16816(d, ah[mt], bl[nt][h * 2], bl[nt][h * 2 + 1]);
                        mma16816(d, al[mt], bh[nt][h * 2], bh[nt][h * 2 + 1]);
                    }
        }
        if (kc < 15) {
            int jn = (kc + 1) * 64;
            #pragma unroll
            for (int cc = 0; cc < 4; cc++) {
                uint32_t e4[4] = {evr[cc].x, evr[cc].y, evr[cc].z, evr[cc].w};
                uint32_t hq[4], lq[4];
                #pragma unroll
                for (int p = 0; p < 4; p++) {
                    __nv_bfloat162 e2 = *(__nv_bfloat162*)&e4[p];
                    int jj = jn + ahalf * 32 + cc * 8 + p * 2;
                    float w0 = __expf(fmaxf(fmaf(__bfloat162float(e2.x), iz, -Ts[jj]), 0.f));
                    float w1 = __expf(fmaxf(fmaf(__bfloat162float(e2.y), iz, -Ts[jj + 1]), 0.f));
                    z2 += w0 + w1;
                    __nv_bfloat16 h0 = __float2bfloat16(w0), h1 = __float2bfloat16(w1);
                    __nv_bfloat162 hp; hp.x = h0; hp.y = h1;
                    hq[p] = *(uint32_t*)&hp;
                    lq[p] = pack2bf(w0 - __bfloat162float(h0), w1 - __bfloat162float(h1));
                }
                int c4 = ahalf * 4 + cc;
                uint32_t sw = nbase + arow * 128 + ((c4 ^ aswr) << 4);
                *(uint4*)(smem + 0 + sw) = *(uint4*)hq;
                *(uint4*)(smem + 16384 + sw) = *(uint4*)lq;
            }
        }
    }

    // z2 reduce: 2 threads per row (adjacent lanes)
    z2 += __shfl_xor_sync(0xffffffffu, z2, 1);
    if (ahalf == 0) zrow[arow] = z2;
    __syncthreads();

    #pragma unroll
    for (int mt = 0; mt < 2; mt++)
        #pragma unroll
        for (int hh = 0; hh < 2; hh++) {
            int rl = wm * 32 + mt * 16 + r + hh * 8;
            int rowg = i0 + rl;
            float iz2 = 1.f / zrow[rl];
            #pragma unroll
            for (int nt8 = 0; nt8 < 8; nt8++) {
                int col = c0 + wn * 64 + nt8 * 8 + q * 2;
                size_t base = ((size_t)b * HW + rowg) * CCH + col;
                float2 xv = *(const float2*)&x[base];
                float2 o;
                o.x = xv.x + acc[mt][nt8][hh * 2 + 0] * iz2;
                o.y = xv.y + acc[mt][nt8][hh * 2 + 1] * iz2;
                *(float2*)&out[base] = o;
            }
        }
}

// ---------------------------------------------------------------------------
extern "C" void kernel_launch(void* const* d_in, const int* in_sizes, int n_in,
                              void* d_out, int out_size)
{
    (void)in_sizes; (void)n_in; (void)out_size;
    const float* x      = (const float*)d_in[0];
    const float* emb_W  = (const float*)d_in[1];
    const float* emb_b  = (const float*)d_in[2];
    const float* attn_W = (const float*)d_in[3];
    const float* attn_b = (const float*)d_in[4];
    const float* thr_W  = (const float*)d_in[5];
    const float* thr_b  = (const float*)d_in[6];
    float* out = (float*)d_out;

    __nv_bfloat16 *wEh, *wEl, *wAh, *wAl;
    cudaGetSymbolAddress((void**)&wEh, g_wEh);
    cudaGetSymbolAddress((void**)&wEl, g_wEl);
    cudaGetSymbolAddress((void**)&wAh, g_wAh);
    cudaGetSymbolAddress((void**)&wAl, g_wAl);

    split_f32<<<16, 256>>>(emb_W, wEh, wEl, FF * CCH / 4);
    split_f32<<<64, 256>>>(attn_W, wAh, wAl, CCH * CCH / 4);

    cudaFuncSetAttribute(hmma_emb, cudaFuncAttributeMaxDynamicSharedMemorySize, 2 * E_ST);
    hmma_emb<<<256, 128, 2 * E_ST>>>(x, emb_b);

    cudaFuncSetAttribute(hmma_short, cudaFuncAttributeMaxDynamicSharedMemorySize, 2 * S_ST);
    hmma_short<<<dim3(256, 2), 256, 2 * S_ST>>>(x, attn_b);

    aux_kernel<<<4096, 256>>>(thr_W, thr_b);

    cudaFuncSetAttribute(gram_ev, cudaFuncAttributeMaxDynamicSharedMemorySize, G_SMEM);
    gram_ev<<<dim3(8, 32), 256, G_SMEM>>>();

    cudaFuncSetAttribute(attn_out, cudaFuncAttributeMaxDynamicSharedMemorySize, O_SMEM);
    attn_out<<<dim3(8, 2, 32), 256, O_SMEM>>>(x, out);
}